// round 2
// baseline (speedup 1.0000x reference)
#include <cuda_runtime.h>
#include <cuda_bf16.h>
#include <math.h>

// Problem constants
#define BB     8
#define NN     1024
#define DIMX   768
#define HEADS  8
#define HD     96
#define NEXP   24
#define TOK    (BB*NN)          // 8192
#define NPAIR  (TOK*HEADS)      // 65536
#define MAX_TILES 1072
#define PAIRS_CAP (MAX_TILES*64)
#define OUT_N  (TOK*DIMX)       // 6291456

// ---------------- scratch (static device globals; no allocation) ----------------
__device__ float g_k[TOK*HD];
__device__ float g_v[TOK*HD];
__device__ float g_q[NPAIR*HD];
__device__ float g_o[NPAIR*HD];
__device__ float g_gates[NPAIR];
__device__ int   g_topi[NPAIR];
__device__ float g_me[NEXP];
__device__ float g_zsum;
__device__ int   g_counts[NEXP];
__device__ int   g_cursor[NEXP];
__device__ int   g_pairs[PAIRS_CAP];
__device__ int   g_tile_e[MAX_TILES];
__device__ int   g_tile_row0[MAX_TILES];
__device__ int   g_tile_nr[MAX_TILES];

// ---------------- init: zero per-call state + output ----------------
__global__ void init_kernel(float* __restrict__ out)
{
    int idx = blockIdx.x * blockDim.x + threadIdx.x;
    if (idx < OUT_N)     out[idx] = 0.f;
    if (idx < PAIRS_CAP) g_pairs[idx] = -1;
    if (idx < NEXP)      { g_me[idx] = 0.f; g_counts[idx] = 0; }
    if (idx == 0)        g_zsum = 0.f;
}

// ---------------- gating: logits, softmax, top-8, aux accumulators ----------------
__global__ __launch_bounds__(128) void gate_kernel(
    const float* __restrict__ x, const float* __restrict__ Wg,
    const int* __restrict__ task_p)
{
    __shared__ float xs[DIMX];
    __shared__ float lg[NEXP];
    __shared__ float ps[NEXP];
    int t   = blockIdx.x;
    int tid = threadIdx.x;
    for (int i = tid; i < DIMX; i += blockDim.x) xs[i] = x[t*DIMX + i];
    __syncthreads();
    int task = task_p[0];
    if (tid < NEXP) {
        const float* w = Wg + (size_t)task*DIMX*NEXP + tid;
        float s = 0.f;
        #pragma unroll 4
        for (int d = 0; d < DIMX; d++) s += xs[d] * w[d*NEXP];
        lg[tid] = s;
    }
    __syncthreads();
    if (tid == 0) {
        float mx = -1e30f;
        for (int e = 0; e < NEXP; e++) mx = fmaxf(mx, lg[e]);
        float sum = 0.f;
        for (int e = 0; e < NEXP; e++) { float v = __expf(lg[e]-mx); ps[e] = v; sum += v; }
        float inv = 1.f/sum;
        float lse = mx + __logf(sum);
        atomicAdd(&g_zsum, lse*lse);
        for (int e = 0; e < NEXP; e++) ps[e] *= inv;
    }
    __syncthreads();
    if (tid < NEXP) atomicAdd(&g_me[tid], ps[tid]);
    if (tid == 0) {
        float topg[HEADS]; int topi[HEADS];
        float gsum = 0.f;
        for (int h = 0; h < HEADS; h++) {
            int bi = 0; float bv = ps[0];
            for (int e = 1; e < NEXP; e++) if (ps[e] > bv) { bv = ps[e]; bi = e; }
            topg[h] = bv; topi[h] = bi; ps[bi] = -1.f; gsum += bv;
            atomicAdd(&g_counts[bi], 1);
        }
        float dn = 1.f/(gsum + 1e-6f);
        for (int h = 0; h < HEADS; h++) {
            g_gates[t*HEADS + h] = topg[h]*dn;
            g_topi [t*HEADS + h] = topi[h];
        }
    }
}

// ---------------- scan: tile table + aux loss ----------------
__global__ void scan_kernel(float* __restrict__ out, int out_size)
{
    if (threadIdx.x != 0 || blockIdx.x != 0) return;
    int base = 0, tile = 0;
    for (int e = 0; e < NEXP; e++) {
        int c = g_counts[e];
        g_cursor[e] = base;
        int nt = (c + 63) >> 6;
        for (int k = 0; k < nt; k++) {
            g_tile_e[tile]    = e;
            g_tile_row0[tile] = base + k*64;
            g_tile_nr[tile]   = min(64, c - k*64);
            tile++;
        }
        base += nt*64;
    }
    for (; tile < MAX_TILES; tile++) g_tile_e[tile] = -1;

    float metot = 0.f;
    for (int e = 0; e < NEXP; e++) metot += g_me[e];
    float sw = 0.f;
    for (int e = 0; e < NEXP; e++) {
        float fe = (float)g_counts[e] / (float)NPAIR;
        sw += (g_me[e]/metot) * fe;
    }
    sw *= (float)NEXP;
    float z   = g_zsum / (float)TOK;
    float aux = 0.1f*sw + 0.001f*z;
    if (out_size > OUT_N) out[OUT_N] = aux;
}

// ---------------- scatter: build per-expert pair lists ----------------
__global__ void scatter_kernel()
{
    int idx = blockIdx.x*blockDim.x + threadIdx.x;
    if (idx >= NPAIR) return;
    int e   = g_topi[idx];
    int pos = atomicAdd(&g_cursor[e], 1);
    g_pairs[pos] = idx;
}

// ---------------- kv projection: [8192,768] @ [768,192] + bias ----------------
__global__ __launch_bounds__(256) void kv_kernel(
    const float* __restrict__ x, const float* __restrict__ Wkv,
    const float* __restrict__ bkv)
{
    __shared__ float Xs[64*33];
    __shared__ float Ws[32*192];
    int row0 = blockIdx.x*64;
    int tid = threadIdx.x;
    int ty = tid >> 4, tx = tid & 15;
    float acc[4][12];
    #pragma unroll
    for (int a = 0; a < 4; a++)
        #pragma unroll
        for (int c = 0; c < 12; c++) acc[a][c] = 0.f;

    for (int kc = 0; kc < DIMX; kc += 32) {
        for (int l = tid; l < 64*32; l += 256) {
            int r = l >> 5, kk = l & 31;
            Xs[r*33 + kk] = x[(size_t)(row0+r)*DIMX + kc + kk];
        }
        for (int l = tid; l < 32*192; l += 256) {
            int kk = l / 192, c = l % 192;
            Ws[kk*192 + c] = Wkv[(size_t)(kc+kk)*192 + c];
        }
        __syncthreads();
        #pragma unroll 4
        for (int kk = 0; kk < 32; kk++) {
            float a0 = Xs[(ty*4+0)*33 + kk];
            float a1 = Xs[(ty*4+1)*33 + kk];
            float a2 = Xs[(ty*4+2)*33 + kk];
            float a3 = Xs[(ty*4+3)*33 + kk];
            #pragma unroll
            for (int c = 0; c < 12; c++) {
                float bv = Ws[kk*192 + tx + c*16];
                acc[0][c] += a0*bv; acc[1][c] += a1*bv;
                acc[2][c] += a2*bv; acc[3][c] += a3*bv;
            }
        }
        __syncthreads();
    }
    #pragma unroll
    for (int ri = 0; ri < 4; ri++) {
        int r = row0 + ty*4 + ri;
        #pragma unroll
        for (int c = 0; c < 12; c++) {
            int col = tx + c*16;
            float v = acc[ri][c] + bkv[col];
            if (col < HD) g_k[r*HD + col] = v;
            else          g_v[r*HD + col - HD] = v;
        }
    }
}

// ---------------- grouped q projection: gathered rows @ W1[e] ----------------
__global__ __launch_bounds__(256) void q_kernel(
    const float* __restrict__ x, const float* __restrict__ W1)
{
    int tile = blockIdx.x;
    int e = g_tile_e[tile];
    if (e < 0) return;
    int row0 = g_tile_row0[tile], nr = g_tile_nr[tile];
    __shared__ float Xs[64*33];
    __shared__ float Ws[32*HD];
    __shared__ int   prs[64];
    int tid = threadIdx.x;
    int ty = tid >> 4, tx = tid & 15;
    if (tid < 64) prs[tid] = (tid < nr) ? g_pairs[row0 + tid] : -1;
    __syncthreads();

    float acc[4][6];
    #pragma unroll
    for (int a = 0; a < 4; a++)
        #pragma unroll
        for (int c = 0; c < 6; c++) acc[a][c] = 0.f;

    const float* Wb = W1 + (size_t)e*DIMX*HD;
    for (int kc = 0; kc < DIMX; kc += 32) {
        for (int l = tid; l < 64*32; l += 256) {
            int r = l >> 5, kk = l & 31;
            int p = prs[r];
            Xs[r*33 + kk] = (p >= 0) ? x[(size_t)(p>>3)*DIMX + kc + kk] : 0.f;
        }
        for (int l = tid; l < 32*HD; l += 256) {
            int kk = l / HD, c = l % HD;
            Ws[kk*HD + c] = Wb[(size_t)(kc+kk)*HD + c];
        }
        __syncthreads();
        #pragma unroll 4
        for (int kk = 0; kk < 32; kk++) {
            float a0 = Xs[(ty*4+0)*33 + kk];
            float a1 = Xs[(ty*4+1)*33 + kk];
            float a2 = Xs[(ty*4+2)*33 + kk];
            float a3 = Xs[(ty*4+3)*33 + kk];
            #pragma unroll
            for (int c = 0; c < 6; c++) {
                float bv = Ws[kk*HD + tx + c*16];
                acc[0][c] += a0*bv; acc[1][c] += a1*bv;
                acc[2][c] += a2*bv; acc[3][c] += a3*bv;
            }
        }
        __syncthreads();
    }
    #pragma unroll
    for (int ri = 0; ri < 4; ri++) {
        int p = prs[ty*4 + ri];
        if (p >= 0) {
            #pragma unroll
            for (int c = 0; c < 6; c++)
                g_q[(size_t)p*HD + tx + c*16] = acc[ri][c];
        }
    }
}

// ---------------- flash attention: per (b, h, 64-row q tile) ----------------
__global__ __launch_bounds__(256, 2) void attn_kernel()
{
    extern __shared__ float sm[];
    float* Qs = sm;               // [64][97]
    float* Kt = Qs + 64*97;       // [96][65]  (K transposed)
    float* Vs = Kt + 96*65;       // [64][96]
    float* Ss = Vs + 64*96;       // [64][65]
    float* mS = Ss + 64*65;       // [64]
    float* lS = mS + 64;          // [64]
    float* cS = lS + 64;          // [64]

    int tid = threadIdx.x;
    int ty = tid >> 4, tx = tid & 15;
    int qt = blockIdx.x, h = blockIdx.y, b = blockIdx.z;
    int t0 = b*NN + qt*64;

    for (int l = tid; l < 64*HD; l += 256) {
        int i = l / HD, c = l % HD;
        Qs[i*97 + c] = g_q[((size_t)(t0+i)*HEADS + h)*HD + c];
    }
    if (tid < 64) { mS[tid] = -1e30f; lS[tid] = 0.f; }
    float O[4][6];
    #pragma unroll
    for (int a = 0; a < 4; a++)
        #pragma unroll
        for (int c = 0; c < 6; c++) O[a][c] = 0.f;
    __syncthreads();

    const float SC = 0.10206207261596577f;  // 96^-0.5

    for (int jt = 0; jt < NN; jt += 64) {
        for (int l = tid; l < 64*HD; l += 256) {
            int j = l / HD, c = l % HD;
            int gj = b*NN + jt + j;
            Kt[c*65 + j] = g_k[(size_t)gj*HD + c];
            Vs[j*HD + c] = g_v[(size_t)gj*HD + c];
        }
        __syncthreads();

        float s[4][4];
        #pragma unroll
        for (int a = 0; a < 4; a++)
            #pragma unroll
            for (int c = 0; c < 4; c++) s[a][c] = 0.f;
        #pragma unroll 4
        for (int c = 0; c < HD; c++) {
            float a0 = Qs[(ty*4+0)*97 + c];
            float a1 = Qs[(ty*4+1)*97 + c];
            float a2 = Qs[(ty*4+2)*97 + c];
            float a3 = Qs[(ty*4+3)*97 + c];
            float b0 = Kt[c*65 + tx];
            float b1 = Kt[c*65 + tx + 16];
            float b2 = Kt[c*65 + tx + 32];
            float b3 = Kt[c*65 + tx + 48];
            s[0][0]+=a0*b0; s[0][1]+=a0*b1; s[0][2]+=a0*b2; s[0][3]+=a0*b3;
            s[1][0]+=a1*b0; s[1][1]+=a1*b1; s[1][2]+=a1*b2; s[1][3]+=a1*b3;
            s[2][0]+=a2*b0; s[2][1]+=a2*b1; s[2][2]+=a2*b2; s[2][3]+=a2*b3;
            s[3][0]+=a3*b0; s[3][1]+=a3*b1; s[3][2]+=a3*b2; s[3][3]+=a3*b3;
        }
        #pragma unroll
        for (int ri = 0; ri < 4; ri++)
            #pragma unroll
            for (int cj = 0; cj < 4; cj++)
                Ss[(ty*4+ri)*65 + tx + cj*16] = s[ri][cj]*SC;
        __syncthreads();

        if (tid < 64) {
            float m = mS[tid], mn = m;
            float* row = Ss + tid*65;
            for (int j = 0; j < 64; j++) mn = fmaxf(mn, row[j]);
            float corr = __expf(m - mn);
            float ls = 0.f;
            for (int j = 0; j < 64; j++) {
                float pv = __expf(row[j] - mn);
                row[j] = pv; ls += pv;
            }
            lS[tid] = lS[tid]*corr + ls;
            mS[tid] = mn; cS[tid] = corr;
        }
        __syncthreads();

        #pragma unroll
        for (int ri = 0; ri < 4; ri++) {
            float cr = cS[ty*4 + ri];
            #pragma unroll
            for (int c = 0; c < 6; c++) O[ri][c] *= cr;
        }
        #pragma unroll 4
        for (int j = 0; j < 64; j++) {
            float p0 = Ss[(ty*4+0)*65 + j];
            float p1 = Ss[(ty*4+1)*65 + j];
            float p2 = Ss[(ty*4+2)*65 + j];
            float p3 = Ss[(ty*4+3)*65 + j];
            #pragma unroll
            for (int c = 0; c < 6; c++) {
                float vv = Vs[j*HD + tx + c*16];
                O[0][c] += p0*vv; O[1][c] += p1*vv;
                O[2][c] += p2*vv; O[3][c] += p3*vv;
            }
        }
        __syncthreads();
    }

    #pragma unroll
    for (int ri = 0; ri < 4; ri++) {
        int r = ty*4 + ri;
        float inv = 1.f/lS[r];
        #pragma unroll
        for (int c = 0; c < 6; c++)
            g_o[((size_t)(t0+r)*HEADS + h)*HD + tx + c*16] = O[ri][c]*inv;
    }
}

// ---------------- grouped reduce: (gates*o) @ W2[e] -> atomic scatter into out --------
__global__ __launch_bounds__(256) void reduce_kernel(
    const float* __restrict__ W2, float* __restrict__ out)
{
    int tile = blockIdx.x;
    int e = g_tile_e[tile];
    if (e < 0) return;
    int c0 = blockIdx.y*64;
    int row0 = g_tile_row0[tile], nr = g_tile_nr[tile];
    __shared__ float Os[64*97];
    __shared__ float Ws[48*64];
    __shared__ int   prs[64];
    __shared__ float gs[64];
    int tid = threadIdx.x;
    int ty = tid >> 4, tx = tid & 15;
    if (tid < 64) {
        int p = (tid < nr) ? g_pairs[row0 + tid] : -1;
        prs[tid] = p;
        gs[tid]  = (p >= 0) ? g_gates[p] : 0.f;
    }
    __syncthreads();
    for (int l = tid; l < 64*HD; l += 256) {
        int r = l / HD, d = l % HD;
        int p = prs[r];
        Os[r*97 + d] = (p >= 0) ? g_o[(size_t)p*HD + d]*gs[r] : 0.f;
    }

    float acc[4][4];
    #pragma unroll
    for (int a = 0; a < 4; a++)
        #pragma unroll
        for (int c = 0; c < 4; c++) acc[a][c] = 0.f;

    const float* Wb = W2 + (size_t)e*HD*DIMX;
    for (int dc = 0; dc < HD; dc += 48) {
        for (int l = tid; l < 48*64; l += 256) {
            int d = l >> 6, c = l & 63;
            Ws[d*64 + c] = Wb[(size_t)(dc+d)*DIMX + c0 + c];
        }
        __syncthreads();
        #pragma unroll 4
        for (int d = 0; d < 48; d++) {
            float a0 = Os[(ty*4+0)*97 + dc + d];
            float a1 = Os[(ty*4+1)*97 + dc + d];
            float a2 = Os[(ty*4+2)*97 + dc + d];
            float a3 = Os[(ty*4+3)*97 + dc + d];
            float b0 = Ws[d*64 + tx];
            float b1 = Ws[d*64 + tx + 16];
            float b2 = Ws[d*64 + tx + 32];
            float b3 = Ws[d*64 + tx + 48];
            acc[0][0]+=a0*b0; acc[0][1]+=a0*b1; acc[0][2]+=a0*b2; acc[0][3]+=a0*b3;
            acc[1][0]+=a1*b0; acc[1][1]+=a1*b1; acc[1][2]+=a1*b2; acc[1][3]+=a1*b3;
            acc[2][0]+=a2*b0; acc[2][1]+=a2*b1; acc[2][2]+=a2*b2; acc[2][3]+=a2*b3;
            acc[3][0]+=a3*b0; acc[3][1]+=a3*b1; acc[3][2]+=a3*b2; acc[3][3]+=a3*b3;
        }
        __syncthreads();
    }
    #pragma unroll
    for (int ri = 0; ri < 4; ri++) {
        int p = prs[ty*4 + ri];
        if (p >= 0) {
            int t = p >> 3;
            float* op = out + (size_t)t*DIMX + c0;
            #pragma unroll
            for (int c = 0; c < 4; c++)
                atomicAdd(op + tx + c*16, acc[ri][c]);
        }
    }
}

// ---------------- launch ----------------
extern "C" void kernel_launch(void* const* d_in, const int* in_sizes, int n_in,
                              void* d_out, int out_size)
{
    const float* x    = (const float*)d_in[0];
    const float* Wg   = (const float*)d_in[1];
    const float* W1   = (const float*)d_in[2];
    const float* W2   = (const float*)d_in[3];
    const float* Wkv  = (const float*)d_in[4];
    const float* bkv  = (const float*)d_in[5];
    const int*   task = (const int*)  d_in[6];
    float* out = (float*)d_out;

    const int attn_smem = (64*97 + 96*65 + 64*96 + 64*65 + 192) * (int)sizeof(float);
    cudaFuncSetAttribute(attn_kernel, cudaFuncAttributeMaxDynamicSharedMemorySize, attn_smem);

    init_kernel<<<(OUT_N + 255)/256, 256>>>(out);
    gate_kernel<<<TOK, 128>>>(x, Wg, task);
    scan_kernel<<<1, 32>>>(out, out_size);
    scatter_kernel<<<NPAIR/256, 256>>>();
    kv_kernel<<<TOK/64, 256>>>(x, Wkv, bkv);
    q_kernel<<<MAX_TILES, 256>>>(x, W1);
    attn_kernel<<<dim3(NN/64, HEADS, BB), 256, attn_smem>>>();
    reduce_kernel<<<dim3(MAX_TILES, DIMX/64), 256>>>(W2, out);
}

// round 6
// speedup vs baseline: 1.0028x; 1.0028x over previous
#include <cuda_runtime.h>
#include <cuda_bf16.h>
#include <math.h>

// Problem constants
#define BB     8
#define NN     1024
#define DIMX   768
#define HEADS  8
#define HD     96
#define NEXP   24
#define TOK    (BB*NN)          // 8192
#define NPAIR  (TOK*HEADS)      // 65536
#define MAX_TILES 1072
#define PAIRS_CAP (MAX_TILES*64)
#define OUT_N  (TOK*DIMX)       // 6291456

typedef unsigned long long u64;

// packed f32x2 FMA: d.lo += a.lo*b.lo ; d.hi += a.hi*b.hi   (PTX 8.6, sm_100+)
__device__ __forceinline__ void ffma2(u64 &d, u64 a, u64 b) {
    asm("fma.rn.f32x2 %0, %1, %2, %0;" : "+l"(d) : "l"(a), "l"(b));
}
__device__ __forceinline__ float hadd2(u64 v) {
    float lo, hi;
    asm("mov.b64 {%0,%1}, %2;" : "=f"(lo), "=f"(hi) : "l"(v));
    return lo + hi;
}
__device__ __forceinline__ u64 lds64(const float* p) {
    return *reinterpret_cast<const u64*>(p);
}

// ---------------- scratch (static device globals; no allocation) ----------------
__device__ __align__(16) float g_k[TOK*HD];
__device__ __align__(16) float g_v[TOK*HD];
__device__ __align__(16) float g_q[NPAIR*HD];
__device__ __align__(16) float g_o[NPAIR*HD];
__device__ float g_gates[NPAIR];
__device__ int   g_topi[NPAIR];
__device__ float g_me[NEXP];
__device__ float g_zsum;
__device__ int   g_counts[NEXP];
__device__ int   g_cursor[NEXP];
__device__ int   g_pairs[PAIRS_CAP];
__device__ int   g_tile_e[MAX_TILES];
__device__ int   g_tile_row0[MAX_TILES];
__device__ int   g_tile_nr[MAX_TILES];

// ---------------- init ----------------
__global__ void init_kernel(float* __restrict__ out)
{
    int idx = blockIdx.x * blockDim.x + threadIdx.x;
    if (idx < OUT_N)     out[idx] = 0.f;
    if (idx < PAIRS_CAP) g_pairs[idx] = -1;
    if (idx < NEXP)      { g_me[idx] = 0.f; g_counts[idx] = 0; }
    if (idx == 0)        g_zsum = 0.f;
}

// ---------------- gating ----------------
__global__ __launch_bounds__(128) void gate_kernel(
    const float* __restrict__ x, const float* __restrict__ Wg,
    const int* __restrict__ task_p)
{
    __shared__ float xs[DIMX];
    __shared__ float lg[NEXP];
    __shared__ float ps[NEXP];
    int t   = blockIdx.x;
    int tid = threadIdx.x;
    for (int i = tid; i < DIMX; i += blockDim.x) xs[i] = x[t*DIMX + i];
    __syncthreads();
    int task = task_p[0];
    if (tid < NEXP) {
        const float* w = Wg + (size_t)task*DIMX*NEXP + tid;
        float s = 0.f;
        #pragma unroll 4
        for (int d = 0; d < DIMX; d++) s += xs[d] * w[d*NEXP];
        lg[tid] = s;
    }
    __syncthreads();
    if (tid == 0) {
        float mx = -1e30f;
        for (int e = 0; e < NEXP; e++) mx = fmaxf(mx, lg[e]);
        float sum = 0.f;
        for (int e = 0; e < NEXP; e++) { float v = __expf(lg[e]-mx); ps[e] = v; sum += v; }
        float inv = 1.f/sum;
        float lse = mx + __logf(sum);
        atomicAdd(&g_zsum, lse*lse);
        for (int e = 0; e < NEXP; e++) ps[e] *= inv;
    }
    __syncthreads();
    if (tid < NEXP) atomicAdd(&g_me[tid], ps[tid]);
    if (tid == 0) {
        float topg[HEADS]; int topi[HEADS];
        float gsum = 0.f;
        for (int h = 0; h < HEADS; h++) {
            int bi = 0; float bv = ps[0];
            for (int e = 1; e < NEXP; e++) if (ps[e] > bv) { bv = ps[e]; bi = e; }
            topg[h] = bv; topi[h] = bi; ps[bi] = -1.f; gsum += bv;
            atomicAdd(&g_counts[bi], 1);
        }
        float dn = 1.f/(gsum + 1e-6f);
        for (int h = 0; h < HEADS; h++) {
            g_gates[t*HEADS + h] = topg[h]*dn;
            g_topi [t*HEADS + h] = topi[h];
        }
    }
}

// ---------------- scan: tile table + aux loss ----------------
__global__ void scan_kernel(float* __restrict__ out, int out_size)
{
    if (threadIdx.x != 0 || blockIdx.x != 0) return;
    int base = 0, tile = 0;
    for (int e = 0; e < NEXP; e++) {
        int c = g_counts[e];
        g_cursor[e] = base;
        int nt = (c + 63) >> 6;
        for (int k = 0; k < nt; k++) {
            g_tile_e[tile]    = e;
            g_tile_row0[tile] = base + k*64;
            g_tile_nr[tile]   = min(64, c - k*64);
            tile++;
        }
        base += nt*64;
    }
    for (; tile < MAX_TILES; tile++) g_tile_e[tile] = -1;

    float metot = 0.f;
    for (int e = 0; e < NEXP; e++) metot += g_me[e];
    float sw = 0.f;
    for (int e = 0; e < NEXP; e++) {
        float fe = (float)g_counts[e] / (float)NPAIR;
        sw += (g_me[e]/metot) * fe;
    }
    sw *= (float)NEXP;
    float z   = g_zsum / (float)TOK;
    float aux = 0.1f*sw + 0.001f*z;
    if (out_size > OUT_N) out[OUT_N] = aux;
}

// ---------------- scatter ----------------
__global__ void scatter_kernel()
{
    int idx = blockIdx.x*blockDim.x + threadIdx.x;
    if (idx >= NPAIR) return;
    int e   = g_topi[idx];
    int pos = atomicAdd(&g_cursor[e], 1);
    g_pairs[pos] = idx;
}

// ---------------- kv projection (half = 0:K cols 0..95, 1:V cols 96..191) ------
__global__ __launch_bounds__(256) void kv_kernel(
    const float* __restrict__ x, const float* __restrict__ Wkv,
    const float* __restrict__ bkv)
{
    __shared__ __align__(16) float Xs[64*34];
    __shared__ __align__(16) float Wt[96*34];   // Wt[c][k] transposed, k contiguous
    int row0 = blockIdx.x*64;
    int half = blockIdx.y;
    int tid = threadIdx.x;
    int ty = tid >> 4, tx = tid & 15;

    u64 acc[4][6];
    #pragma unroll
    for (int a = 0; a < 4; a++)
        #pragma unroll
        for (int c = 0; c < 6; c++) acc[a][c] = 0ULL;

    for (int kc = 0; kc < DIMX; kc += 32) {
        for (int l = tid; l < 64*32; l += 256) {
            int r = l >> 5, kk = l & 31;
            Xs[r*34 + kk] = x[(size_t)(row0+r)*DIMX + kc + kk];
        }
        for (int l = tid; l < 32*96; l += 256) {
            int kk = l / 96, c = l % 96;
            Wt[c*34 + kk] = Wkv[(size_t)(kc+kk)*192 + half*96 + c];
        }
        __syncthreads();
        #pragma unroll 2
        for (int kp = 0; kp < 16; kp++) {
            u64 a0 = lds64(&Xs[(ty*4+0)*34 + 2*kp]);
            u64 a1 = lds64(&Xs[(ty*4+1)*34 + 2*kp]);
            u64 a2 = lds64(&Xs[(ty*4+2)*34 + 2*kp]);
            u64 a3 = lds64(&Xs[(ty*4+3)*34 + 2*kp]);
            #pragma unroll
            for (int c = 0; c < 6; c++) {
                u64 bv = lds64(&Wt[(tx+16*c)*34 + 2*kp]);
                ffma2(acc[0][c], a0, bv); ffma2(acc[1][c], a1, bv);
                ffma2(acc[2][c], a2, bv); ffma2(acc[3][c], a3, bv);
            }
        }
        __syncthreads();
    }
    #pragma unroll
    for (int ri = 0; ri < 4; ri++) {
        int r = row0 + ty*4 + ri;
        #pragma unroll
        for (int c = 0; c < 6; c++) {
            int col = tx + 16*c;
            float v = hadd2(acc[ri][c]) + bkv[half*96 + col];
            if (half == 0) g_k[(size_t)r*HD + col] = v;
            else           g_v[(size_t)r*HD + col] = v;
        }
    }
}

// ---------------- grouped q projection ----------------
__global__ __launch_bounds__(256) void q_kernel(
    const float* __restrict__ x, const float* __restrict__ W1)
{
    int tile = blockIdx.x;
    int e = g_tile_e[tile];
    if (e < 0) return;
    int row0 = g_tile_row0[tile], nr = g_tile_nr[tile];
    __shared__ __align__(16) float Xs[64*34];
    __shared__ __align__(16) float Wt[96*34];
    __shared__ int prs[64];
    int tid = threadIdx.x;
    int ty = tid >> 4, tx = tid & 15;
    if (tid < 64) prs[tid] = (tid < nr) ? g_pairs[row0 + tid] : -1;
    __syncthreads();

    u64 acc[4][6];
    #pragma unroll
    for (int a = 0; a < 4; a++)
        #pragma unroll
        for (int c = 0; c < 6; c++) acc[a][c] = 0ULL;

    const float* Wb = W1 + (size_t)e*DIMX*HD;
    for (int kc = 0; kc < DIMX; kc += 32) {
        for (int l = tid; l < 64*32; l += 256) {
            int r = l >> 5, kk = l & 31;
            int p = prs[r];
            Xs[r*34 + kk] = (p >= 0) ? x[(size_t)(p>>3)*DIMX + kc + kk] : 0.f;
        }
        for (int l = tid; l < 32*96; l += 256) {
            int kk = l / 96, c = l % 96;
            Wt[c*34 + kk] = Wb[(size_t)(kc+kk)*HD + c];
        }
        __syncthreads();
        #pragma unroll 2
        for (int kp = 0; kp < 16; kp++) {
            u64 a0 = lds64(&Xs[(ty*4+0)*34 + 2*kp]);
            u64 a1 = lds64(&Xs[(ty*4+1)*34 + 2*kp]);
            u64 a2 = lds64(&Xs[(ty*4+2)*34 + 2*kp]);
            u64 a3 = lds64(&Xs[(ty*4+3)*34 + 2*kp]);
            #pragma unroll
            for (int c = 0; c < 6; c++) {
                u64 bv = lds64(&Wt[(tx+16*c)*34 + 2*kp]);
                ffma2(acc[0][c], a0, bv); ffma2(acc[1][c], a1, bv);
                ffma2(acc[2][c], a2, bv); ffma2(acc[3][c], a3, bv);
            }
        }
        __syncthreads();
    }
    #pragma unroll
    for (int ri = 0; ri < 4; ri++) {
        int p = prs[ty*4 + ri];
        if (p >= 0) {
            #pragma unroll
            for (int c = 0; c < 6; c++)
                g_q[(size_t)p*HD + tx + 16*c] = hadd2(acc[ri][c]);
        }
    }
}

// ---------------- flash attention ----------------
// smem: Qs[64][98], Ks[64][98] (both K-contig), Vt[96][66] (j-contig), Ss[64][66]
__global__ __launch_bounds__(256, 2) void attn_kernel()
{
    extern __shared__ __align__(16) float sm[];
    float* Qs = sm;                 // 64*98
    float* Ks = Qs + 64*98;         // 64*98
    float* Vt = Ks + 64*98;         // 96*66
    float* Ss = Vt + 96*66;         // 64*66
    float* mS = Ss + 64*66;
    float* lS = mS + 64;
    float* cS = lS + 64;

    int tid = threadIdx.x;
    int ty = tid >> 4, tx = tid & 15;
    int qt = blockIdx.x, h = blockIdx.y, b = blockIdx.z;
    int t0 = b*NN + qt*64;

    for (int l = tid; l < 64*HD; l += 256) {
        int i = l / HD, c = l % HD;
        Qs[i*98 + c] = g_q[((size_t)(t0+i)*HEADS + h)*HD + c];
    }
    if (tid < 64) { mS[tid] = -1e30f; lS[tid] = 0.f; }
    float O[4][6];
    #pragma unroll
    for (int a = 0; a < 4; a++)
        #pragma unroll
        for (int c = 0; c < 6; c++) O[a][c] = 0.f;
    __syncthreads();

    const float SC = 0.10206207261596577f;  // 96^-0.5

    for (int jt = 0; jt < NN; jt += 64) {
        for (int l = tid; l < 64*HD; l += 256) {
            int j = l / HD, c = l % HD;
            int gj = b*NN + jt + j;
            Ks[j*98 + c] = g_k[(size_t)gj*HD + c];
            Vt[c*66 + j] = g_v[(size_t)gj*HD + c];
        }
        __syncthreads();

        // ---- S = Q K^T (pairs along c) ----
        u64 s2[4][4];
        #pragma unroll
        for (int a = 0; a < 4; a++)
            #pragma unroll
            for (int c = 0; c < 4; c++) s2[a][c] = 0ULL;
        #pragma unroll 2
        for (int cp = 0; cp < HD/2; cp++) {
            u64 a0 = lds64(&Qs[(ty*4+0)*98 + 2*cp]);
            u64 a1 = lds64(&Qs[(ty*4+1)*98 + 2*cp]);
            u64 a2 = lds64(&Qs[(ty*4+2)*98 + 2*cp]);
            u64 a3 = lds64(&Qs[(ty*4+3)*98 + 2*cp]);
            #pragma unroll
            for (int cj = 0; cj < 4; cj++) {
                u64 bv = lds64(&Ks[(tx+16*cj)*98 + 2*cp]);
                ffma2(s2[0][cj], a0, bv); ffma2(s2[1][cj], a1, bv);
                ffma2(s2[2][cj], a2, bv); ffma2(s2[3][cj], a3, bv);
            }
        }
        #pragma unroll
        for (int ri = 0; ri < 4; ri++)
            #pragma unroll
            for (int cj = 0; cj < 4; cj++)
                Ss[(ty*4+ri)*66 + tx + 16*cj] = hadd2(s2[ri][cj])*SC;
        __syncthreads();

        // ---- online softmax: 4 lanes per row, 16 cols each ----
        {
            int r  = tid >> 2;
            int s4 = tid & 3;
            float* row = Ss + r*66 + s4*16;
            float mloc = -1e30f;
            #pragma unroll
            for (int j = 0; j < 16; j++) mloc = fmaxf(mloc, row[j]);
            mloc = fmaxf(mloc, __shfl_xor_sync(0xffffffffu, mloc, 1));
            mloc = fmaxf(mloc, __shfl_xor_sync(0xffffffffu, mloc, 2));
            float mOld = mS[r];
            float mn = fmaxf(mOld, mloc);
            float ls = 0.f;
            #pragma unroll
            for (int j = 0; j < 16; j++) {
                float pv = __expf(row[j] - mn);
                row[j] = pv; ls += pv;
            }
            ls += __shfl_xor_sync(0xffffffffu, ls, 1);
            ls += __shfl_xor_sync(0xffffffffu, ls, 2);
            if (s4 == 0) {
                float corr = __expf(mOld - mn);
                cS[r] = corr; mS[r] = mn;
                lS[r] = lS[r]*corr + ls;
            }
        }
        __syncthreads();

        // ---- O = O*corr + P V (pairs along j) ----
        u64 o2[4][6];
        #pragma unroll
        for (int a = 0; a < 4; a++)
            #pragma unroll
            for (int c = 0; c < 6; c++) o2[a][c] = 0ULL;
        #pragma unroll 2
        for (int jp = 0; jp < 32; jp++) {
            u64 a0 = lds64(&Ss[(ty*4+0)*66 + 2*jp]);
            u64 a1 = lds64(&Ss[(ty*4+1)*66 + 2*jp]);
            u64 a2 = lds64(&Ss[(ty*4+2)*66 + 2*jp]);
            u64 a3 = lds64(&Ss[(ty*4+3)*66 + 2*jp]);
            #pragma unroll
            for (int cd = 0; cd < 6; cd++) {
                u64 bv = lds64(&Vt[(tx+16*cd)*66 + 2*jp]);
                ffma2(o2[0][cd], a0, bv); ffma2(o2[1][cd], a1, bv);
                ffma2(o2[2][cd], a2, bv); ffma2(o2[3][cd], a3, bv);
            }
        }
        #pragma unroll
        for (int ri = 0; ri < 4; ri++) {
            float cr = cS[ty*4 + ri];
            #pragma unroll
            for (int cd = 0; cd < 6; cd++)
                O[ri][cd] = O[ri][cd]*cr + hadd2(o2[ri][cd]);
        }
        __syncthreads();
    }

    #pragma unroll
    for (int ri = 0; ri < 4; ri++) {
        int r = ty*4 + ri;
        float inv = 1.f/lS[r];
        #pragma unroll
        for (int cd = 0; cd < 6; cd++)
            g_o[((size_t)(t0+r)*HEADS + h)*HD + tx + 16*cd] = O[ri][cd]*inv;
    }
}

// ---------------- grouped reduce: (gates*o) @ W2[e] -> atomic scatter ----------
// Big tiles live in DYNAMIC smem (static is capped at 48KB; 2*64*98 floats = 50176B)
__global__ __launch_bounds__(256) void reduce_kernel(
    const float* __restrict__ W2, float* __restrict__ out)
{
    int tile = blockIdx.x;
    int e = g_tile_e[tile];
    if (e < 0) return;
    int c0 = blockIdx.y*64;
    int row0 = g_tile_row0[tile], nr = g_tile_nr[tile];
    extern __shared__ __align__(16) float rsm[];
    float* Os  = rsm;               // 64*98
    float* W2t = rsm + 64*98;       // 64*98  (W2t[c][d], d contiguous)
    __shared__ int   prs[64];
    __shared__ float gs[64];
    int tid = threadIdx.x;
    int ty = tid >> 4, tx = tid & 15;
    if (tid < 64) {
        int p = (tid < nr) ? g_pairs[row0 + tid] : -1;
        prs[tid] = p;
        gs[tid]  = (p >= 0) ? g_gates[p] : 0.f;
    }
    __syncthreads();
    for (int l = tid; l < 64*HD; l += 256) {
        int r = l / HD, d = l % HD;
        int p = prs[r];
        Os[r*98 + d] = (p >= 0) ? g_o[(size_t)p*HD + d]*gs[r] : 0.f;
    }
    const float* Wb = W2 + (size_t)e*HD*DIMX;
    for (int l = tid; l < HD*64; l += 256) {
        int d = l >> 6, c = l & 63;
        W2t[c*98 + d] = Wb[(size_t)d*DIMX + c0 + c];
    }
    __syncthreads();

    u64 acc[4][4];
    #pragma unroll
    for (int a = 0; a < 4; a++)
        #pragma unroll
        for (int c = 0; c < 4; c++) acc[a][c] = 0ULL;

    #pragma unroll 2
    for (int dp = 0; dp < HD/2; dp++) {
        u64 a0 = lds64(&Os[(ty*4+0)*98 + 2*dp]);
        u64 a1 = lds64(&Os[(ty*4+1)*98 + 2*dp]);
        u64 a2 = lds64(&Os[(ty*4+2)*98 + 2*dp]);
        u64 a3 = lds64(&Os[(ty*4+3)*98 + 2*dp]);
        #pragma unroll
        for (int cj = 0; cj < 4; cj++) {
            u64 bv = lds64(&W2t[(tx+16*cj)*98 + 2*dp]);
            ffma2(acc[0][cj], a0, bv); ffma2(acc[1][cj], a1, bv);
            ffma2(acc[2][cj], a2, bv); ffma2(acc[3][cj], a3, bv);
        }
    }
    #pragma unroll
    for (int ri = 0; ri < 4; ri++) {
        int p = prs[ty*4 + ri];
        if (p >= 0) {
            int t = p >> 3;
            float* op = out + (size_t)t*DIMX + c0;
            #pragma unroll
            for (int cj = 0; cj < 4; cj++)
                atomicAdd(op + tx + 16*cj, hadd2(acc[ri][cj]));
        }
    }
}

// ---------------- launch ----------------
extern "C" void kernel_launch(void* const* d_in, const int* in_sizes, int n_in,
                              void* d_out, int out_size)
{
    const float* x    = (const float*)d_in[0];
    const float* Wg   = (const float*)d_in[1];
    const float* W1   = (const float*)d_in[2];
    const float* W2   = (const float*)d_in[3];
    const float* Wkv  = (const float*)d_in[4];
    const float* bkv  = (const float*)d_in[5];
    const int*   task = (const int*)  d_in[6];
    float* out = (float*)d_out;

    const int attn_smem   = (64*98 + 64*98 + 96*66 + 64*66 + 192) * (int)sizeof(float);
    const int reduce_smem = (64*98 * 2) * (int)sizeof(float);
    cudaFuncSetAttribute(attn_kernel,   cudaFuncAttributeMaxDynamicSharedMemorySize, attn_smem);
    cudaFuncSetAttribute(reduce_kernel, cudaFuncAttributeMaxDynamicSharedMemorySize, reduce_smem);

    init_kernel<<<(OUT_N + 255)/256, 256>>>(out);
    gate_kernel<<<TOK, 128>>>(x, Wg, task);
    scan_kernel<<<1, 32>>>(out, out_size);
    scatter_kernel<<<NPAIR/256, 256>>>();
    kv_kernel<<<dim3(TOK/64, 2), 256>>>(x, Wkv, bkv);
    q_kernel<<<MAX_TILES, 256>>>(x, W1);
    attn_kernel<<<dim3(NN/64, HEADS, BB), 256, attn_smem>>>();
    reduce_kernel<<<dim3(MAX_TILES, DIMX/64), 256, reduce_smem>>>(W2, out);
}

// round 8
// speedup vs baseline: 1.1740x; 1.1708x over previous
#include <cuda_runtime.h>
#include <cuda_bf16.h>
#include <math.h>

// Problem constants
#define BB     8
#define NN     1024
#define DIMX   768
#define HEADS  8
#define HD     96
#define NEXP   24
#define TOK    (BB*NN)          // 8192
#define NPAIR  (TOK*HEADS)      // 65536
#define MAX_TILES 1072
#define PAIRS_CAP (MAX_TILES*64)
#define OUT_N  (TOK*DIMX)       // 6291456

typedef unsigned long long u64;
typedef unsigned int u32;

__device__ __forceinline__ void ffma2(u64 &d, u64 a, u64 b) {
    asm("fma.rn.f32x2 %0, %1, %2, %0;" : "+l"(d) : "l"(a), "l"(b));
}
__device__ __forceinline__ float hadd2(u64 v) {
    float lo, hi;
    asm("mov.b64 {%0,%1}, %2;" : "=f"(lo), "=f"(hi) : "l"(v));
    return lo + hi;
}
__device__ __forceinline__ u64 lds64(const float* p) {
    return *reinterpret_cast<const u64*>(p);
}
__device__ __forceinline__ u32 smem_u32(const void* p) {
    u32 a;
    asm("{ .reg .u64 t; cvta.to.shared.u64 t, %1; cvt.u32.u64 %0, t; }" : "=r"(a) : "l"(p));
    return a;
}
// ---- Ampere-class warp MMA (valid on sm_100; tcgen05 is NOT, harness targets sm_100) ----
__device__ __forceinline__ void ldm_x4(u32 &r0, u32 &r1, u32 &r2, u32 &r3, u32 addr) {
    asm volatile("ldmatrix.sync.aligned.m8n8.x4.shared.b16 {%0,%1,%2,%3}, [%4];"
        : "=r"(r0), "=r"(r1), "=r"(r2), "=r"(r3) : "r"(addr));
}
__device__ __forceinline__ void ldm_x2(u32 &r0, u32 &r1, u32 addr) {
    asm volatile("ldmatrix.sync.aligned.m8n8.x2.shared.b16 {%0,%1}, [%2];"
        : "=r"(r0), "=r"(r1) : "r"(addr));
}
__device__ __forceinline__ void mma_bf16(float* c, u32 a0, u32 a1, u32 a2, u32 a3, u32 b0, u32 b1) {
    asm volatile("mma.sync.aligned.m16n8k16.row.col.f32.bf16.bf16.f32 "
        "{%0,%1,%2,%3}, {%4,%5,%6,%7}, {%8,%9}, {%0,%1,%2,%3};"
        : "+f"(c[0]), "+f"(c[1]), "+f"(c[2]), "+f"(c[3])
        : "r"(a0), "r"(a1), "r"(a2), "r"(a3), "r"(b0), "r"(b1));
}
// pack two floats to bf16x2: lo -> lower 16 bits (k-even element), hi -> upper
__device__ __forceinline__ u32 pack_bf16(float lo, float hi) {
    u32 d;
    asm("cvt.rn.bf16x2.f32 %0, %1, %2;" : "=r"(d) : "f"(hi), "f"(lo));
    return d;
}

// ---------------- scratch ----------------
__device__ __align__(16) float g_k[TOK*HD];
__device__ __align__(16) float g_v[TOK*HD];
__device__ __align__(16) float g_q[NPAIR*HD];
__device__ __align__(16) float g_o[NPAIR*HD];
__device__ float g_gates[NPAIR];
__device__ int   g_topi[NPAIR];
__device__ float g_me[NEXP];
__device__ float g_zsum;
__device__ int   g_counts[NEXP];
__device__ int   g_cursor[NEXP];
__device__ int   g_pairs[PAIRS_CAP];
__device__ int   g_tile_e[MAX_TILES];
__device__ int   g_tile_row0[MAX_TILES];
__device__ int   g_tile_nr[MAX_TILES];

// ---------------- init ----------------
__global__ void init_kernel(float* __restrict__ out)
{
    int idx = blockIdx.x * blockDim.x + threadIdx.x;
    if (idx < OUT_N)     out[idx] = 0.f;
    if (idx < PAIRS_CAP) g_pairs[idx] = -1;
    if (idx < NEXP)      { g_me[idx] = 0.f; g_counts[idx] = 0; }
    if (idx == 0)        g_zsum = 0.f;
}

// ---------------- gating ----------------
__global__ __launch_bounds__(128) void gate_kernel(
    const float* __restrict__ x, const float* __restrict__ Wg,
    const int* __restrict__ task_p)
{
    __shared__ float xs[DIMX];
    __shared__ float lg[NEXP];
    __shared__ float ps[NEXP];
    int t   = blockIdx.x;
    int tid = threadIdx.x;
    for (int i = tid; i < DIMX; i += blockDim.x) xs[i] = x[t*DIMX + i];
    __syncthreads();
    int task = task_p[0];
    if (tid < NEXP) {
        const float* w = Wg + (size_t)task*DIMX*NEXP + tid;
        float s = 0.f;
        #pragma unroll 4
        for (int d = 0; d < DIMX; d++) s += xs[d] * w[d*NEXP];
        lg[tid] = s;
    }
    __syncthreads();
    if (tid == 0) {
        float mx = -1e30f;
        for (int e = 0; e < NEXP; e++) mx = fmaxf(mx, lg[e]);
        float sum = 0.f;
        for (int e = 0; e < NEXP; e++) { float v = __expf(lg[e]-mx); ps[e] = v; sum += v; }
        float inv = 1.f/sum;
        float lse = mx + __logf(sum);
        atomicAdd(&g_zsum, lse*lse);
        for (int e = 0; e < NEXP; e++) ps[e] *= inv;
    }
    __syncthreads();
    if (tid < NEXP) atomicAdd(&g_me[tid], ps[tid]);
    if (tid == 0) {
        float topg[HEADS]; int topi[HEADS];
        float gsum = 0.f;
        for (int h = 0; h < HEADS; h++) {
            int bi = 0; float bv = ps[0];
            for (int e = 1; e < NEXP; e++) if (ps[e] > bv) { bv = ps[e]; bi = e; }
            topg[h] = bv; topi[h] = bi; ps[bi] = -1.f; gsum += bv;
            atomicAdd(&g_counts[bi], 1);
        }
        float dn = 1.f/(gsum + 1e-6f);
        for (int h = 0; h < HEADS; h++) {
            g_gates[t*HEADS + h] = topg[h]*dn;
            g_topi [t*HEADS + h] = topi[h];
        }
    }
}

// ---------------- scan ----------------
__global__ void scan_kernel(float* __restrict__ out, int out_size)
{
    if (threadIdx.x != 0 || blockIdx.x != 0) return;
    int base = 0, tile = 0;
    for (int e = 0; e < NEXP; e++) {
        int c = g_counts[e];
        g_cursor[e] = base;
        int nt = (c + 63) >> 6;
        for (int k = 0; k < nt; k++) {
            g_tile_e[tile]    = e;
            g_tile_row0[tile] = base + k*64;
            g_tile_nr[tile]   = min(64, c - k*64);
            tile++;
        }
        base += nt*64;
    }
    for (; tile < MAX_TILES; tile++) g_tile_e[tile] = -1;

    float metot = 0.f;
    for (int e = 0; e < NEXP; e++) metot += g_me[e];
    float sw = 0.f;
    for (int e = 0; e < NEXP; e++) {
        float fe = (float)g_counts[e] / (float)NPAIR;
        sw += (g_me[e]/metot) * fe;
    }
    sw *= (float)NEXP;
    float z   = g_zsum / (float)TOK;
    float aux = 0.1f*sw + 0.001f*z;
    if (out_size > OUT_N) out[OUT_N] = aux;
}

// ---------------- scatter ----------------
__global__ void scatter_kernel()
{
    int idx = blockIdx.x*blockDim.x + threadIdx.x;
    if (idx >= NPAIR) return;
    int e   = g_topi[idx];
    int pos = atomicAdd(&g_cursor[e], 1);
    g_pairs[pos] = idx;
}

// ---------------- kv projection ----------------
__global__ __launch_bounds__(256) void kv_kernel(
    const float* __restrict__ x, const float* __restrict__ Wkv,
    const float* __restrict__ bkv)
{
    __shared__ __align__(16) float Xs[64*34];
    __shared__ __align__(16) float Wt[96*34];
    int row0 = blockIdx.x*64;
    int half = blockIdx.y;
    int tid = threadIdx.x;
    int ty = tid >> 4, tx = tid & 15;

    u64 acc[4][6];
    #pragma unroll
    for (int a = 0; a < 4; a++)
        #pragma unroll
        for (int c = 0; c < 6; c++) acc[a][c] = 0ULL;

    for (int kc = 0; kc < DIMX; kc += 32) {
        for (int l = tid; l < 64*32; l += 256) {
            int r = l >> 5, kk = l & 31;
            Xs[r*34 + kk] = x[(size_t)(row0+r)*DIMX + kc + kk];
        }
        for (int l = tid; l < 32*96; l += 256) {
            int kk = l / 96, c = l % 96;
            Wt[c*34 + kk] = Wkv[(size_t)(kc+kk)*192 + half*96 + c];
        }
        __syncthreads();
        #pragma unroll 2
        for (int kp = 0; kp < 16; kp++) {
            u64 a0 = lds64(&Xs[(ty*4+0)*34 + 2*kp]);
            u64 a1 = lds64(&Xs[(ty*4+1)*34 + 2*kp]);
            u64 a2 = lds64(&Xs[(ty*4+2)*34 + 2*kp]);
            u64 a3 = lds64(&Xs[(ty*4+3)*34 + 2*kp]);
            #pragma unroll
            for (int c = 0; c < 6; c++) {
                u64 bv = lds64(&Wt[(tx+16*c)*34 + 2*kp]);
                ffma2(acc[0][c], a0, bv); ffma2(acc[1][c], a1, bv);
                ffma2(acc[2][c], a2, bv); ffma2(acc[3][c], a3, bv);
            }
        }
        __syncthreads();
    }
    #pragma unroll
    for (int ri = 0; ri < 4; ri++) {
        int r = row0 + ty*4 + ri;
        #pragma unroll
        for (int c = 0; c < 6; c++) {
            int col = tx + 16*c;
            float v = hadd2(acc[ri][c]) + bkv[half*96 + col];
            if (half == 0) g_k[(size_t)r*HD + col] = v;
            else           g_v[(size_t)r*HD + col] = v;
        }
    }
}

// ---------------- grouped q projection ----------------
__global__ __launch_bounds__(256) void q_kernel(
    const float* __restrict__ x, const float* __restrict__ W1)
{
    int tile = blockIdx.x;
    int e = g_tile_e[tile];
    if (e < 0) return;
    int row0 = g_tile_row0[tile], nr = g_tile_nr[tile];
    __shared__ __align__(16) float Xs[64*34];
    __shared__ __align__(16) float Wt[96*34];
    __shared__ int prs[64];
    int tid = threadIdx.x;
    int ty = tid >> 4, tx = tid & 15;
    if (tid < 64) prs[tid] = (tid < nr) ? g_pairs[row0 + tid] : -1;
    __syncthreads();

    u64 acc[4][6];
    #pragma unroll
    for (int a = 0; a < 4; a++)
        #pragma unroll
        for (int c = 0; c < 6; c++) acc[a][c] = 0ULL;

    const float* Wb = W1 + (size_t)e*DIMX*HD;
    for (int kc = 0; kc < DIMX; kc += 32) {
        for (int l = tid; l < 64*32; l += 256) {
            int r = l >> 5, kk = l & 31;
            int p = prs[r];
            Xs[r*34 + kk] = (p >= 0) ? x[(size_t)(p>>3)*DIMX + kc + kk] : 0.f;
        }
        for (int l = tid; l < 32*96; l += 256) {
            int kk = l / 96, c = l % 96;
            Wt[c*34 + kk] = Wb[(size_t)(kc+kk)*HD + c];
        }
        __syncthreads();
        #pragma unroll 2
        for (int kp = 0; kp < 16; kp++) {
            u64 a0 = lds64(&Xs[(ty*4+0)*34 + 2*kp]);
            u64 a1 = lds64(&Xs[(ty*4+1)*34 + 2*kp]);
            u64 a2 = lds64(&Xs[(ty*4+2)*34 + 2*kp]);
            u64 a3 = lds64(&Xs[(ty*4+3)*34 + 2*kp]);
            #pragma unroll
            for (int c = 0; c < 6; c++) {
                u64 bv = lds64(&Wt[(tx+16*c)*34 + 2*kp]);
                ffma2(acc[0][c], a0, bv); ffma2(acc[1][c], a1, bv);
                ffma2(acc[2][c], a2, bv); ffma2(acc[3][c], a3, bv);
            }
        }
        __syncthreads();
    }
    #pragma unroll
    for (int ri = 0; ri < 4; ri++) {
        int p = prs[ty*4 + ri];
        if (p >= 0) {
            #pragma unroll
            for (int c = 0; c < 6; c++)
                g_q[(size_t)p*HD + tx + 16*c] = hadd2(acc[ri][c]);
        }
    }
}

// ---------------- flash attention via mma.sync bf16 (hi/lo split) -------------
// Block = 256 thr (8 warps), q-tile 128 rows, j-tiles of 64 keys, no-max softmax.
// Warp w owns q-rows 16w..16w+15. S fragments convert to P A-fragments in regs.
#define QS 104
#define KSS 104
#define VS 72
#define O_QH 0
#define O_QL (O_QH + 128*QS*2)
#define O_KH (O_QL + 128*QS*2)
#define O_KL (O_KH + 64*KSS*2)
#define O_VH (O_KL + 64*KSS*2)
#define O_VL (O_VH + 96*VS*2)
#define ATTN_SMEM (O_VL + 96*VS*2)

__global__ __launch_bounds__(256, 1) void attn_mma_kernel()
{
    extern __shared__ __align__(16) char dsm[];
    const u32 sbase = smem_u32(dsm);
    __nv_bfloat16* Qh = (__nv_bfloat16*)(dsm + O_QH);
    __nv_bfloat16* Ql = (__nv_bfloat16*)(dsm + O_QL);
    __nv_bfloat16* Kh = (__nv_bfloat16*)(dsm + O_KH);
    __nv_bfloat16* Kl = (__nv_bfloat16*)(dsm + O_KL);
    __nv_bfloat16* Vh = (__nv_bfloat16*)(dsm + O_VH);
    __nv_bfloat16* Vl = (__nv_bfloat16*)(dsm + O_VL);

    int tid = threadIdx.x, wid = tid >> 5, lane = tid & 31;
    int qt = blockIdx.x, h = blockIdx.y, b = blockIdx.z;
    int t0 = b*NN + qt*128, bN = b*NN;
    int r0 = wid*16;
    const float SC = 0.10206207261596577f;  // 96^-0.5

    // stage Q (scaled, hi/lo split)
    for (int idx = tid; idx < 128*96; idx += 256) {
        int r = idx / 96, c = idx % 96;
        float qv = g_q[((size_t)(t0+r)*HEADS + h)*HD + c] * SC;
        __nv_bfloat16 hi = __float2bfloat16(qv);
        Qh[r*QS + c] = hi;
        Ql[r*QS + c] = __float2bfloat16(qv - __bfloat162float(hi));
    }

    float oC[12][4];
    #pragma unroll
    for (int d = 0; d < 12; d++)
        #pragma unroll
        for (int i = 0; i < 4; i++) oC[d][i] = 0.f;
    float ls01 = 0.f, ls23 = 0.f;

    for (int jt = 0; jt < 16; jt++) {
        // stage K [j][c] and V^T [d][j], hi/lo
        for (int idx = tid; idx < 64*96; idx += 256) {
            int r = idx / 96, c = idx % 96;
            float kv = g_k[(size_t)(bN + jt*64 + r)*HD + c];
            __nv_bfloat16 hi = __float2bfloat16(kv);
            Kh[r*KSS + c] = hi;
            Kl[r*KSS + c] = __float2bfloat16(kv - __bfloat162float(hi));
        }
        for (int idx = tid; idx < 64*96; idx += 256) {
            int j = idx / 96, d = idx % 96;
            float vv = g_v[(size_t)(bN + jt*64 + j)*HD + d];
            __nv_bfloat16 hi = __float2bfloat16(vv);
            Vh[d*VS + j] = hi;
            Vl[d*VS + j] = __float2bfloat16(vv - __bfloat162float(hi));
        }
        __syncthreads();

        // ---- S = Q K^T : 6 k-steps x 8 n-tiles x {hh,hl,lh} ----
        float sC[8][4];
        #pragma unroll
        for (int nt = 0; nt < 8; nt++)
            #pragma unroll
            for (int i = 0; i < 4; i++) sC[nt][i] = 0.f;

        #pragma unroll
        for (int ks = 0; ks < 6; ks++) {
            u32 aoff = (u32)(((r0 + (lane & 15))*QS + ks*16 + ((lane >> 4) & 1)*8) * 2);
            u32 aH0,aH1,aH2,aH3, aL0,aL1,aL2,aL3;
            ldm_x4(aH0,aH1,aH2,aH3, sbase + O_QH + aoff);
            ldm_x4(aL0,aL1,aL2,aL3, sbase + O_QL + aoff);
            #pragma unroll
            for (int nt = 0; nt < 8; nt++) {
                u32 boff = (u32)(((nt*8 + (lane & 7))*KSS + ks*16 + ((lane >> 3) & 1)*8) * 2);
                u32 bH0,bH1, bL0,bL1;
                ldm_x2(bH0,bH1, sbase + O_KH + boff);
                ldm_x2(bL0,bL1, sbase + O_KL + boff);
                mma_bf16(sC[nt], aH0,aH1,aH2,aH3, bH0,bH1);
                mma_bf16(sC[nt], aH0,aH1,aH2,aH3, bL0,bL1);
                mma_bf16(sC[nt], aL0,aL1,aL2,aL3, bH0,bH1);
            }
        }

        // ---- exp + register-direct C->A conversion + row sums ----
        u32 ph0[8], ph1[8], pl0[8], pl1[8];
        #pragma unroll
        for (int nt = 0; nt < 8; nt++) {
            float p0 = __expf(sC[nt][0]);
            float p1 = __expf(sC[nt][1]);
            float p2 = __expf(sC[nt][2]);
            float p3 = __expf(sC[nt][3]);
            ls01 += p0 + p1;
            ls23 += p2 + p3;
            ph0[nt] = pack_bf16(p0, p1);
            ph1[nt] = pack_bf16(p2, p3);
            float q0 = p0 - __bfloat162float(__float2bfloat16(p0));
            float q1 = p1 - __bfloat162float(__float2bfloat16(p1));
            float q2 = p2 - __bfloat162float(__float2bfloat16(p2));
            float q3 = p3 - __bfloat162float(__float2bfloat16(p3));
            pl0[nt] = pack_bf16(q0, q1);
            pl1[nt] = pack_bf16(q2, q3);
        }

        // ---- O += P V : 4 k-steps(j) x 12 d-tiles x {hh,hl,lh} ----
        #pragma unroll
        for (int ks2 = 0; ks2 < 4; ks2++) {
            u32 Ah0 = ph0[2*ks2], Ah1 = ph1[2*ks2], Ah2 = ph0[2*ks2+1], Ah3 = ph1[2*ks2+1];
            u32 Al0 = pl0[2*ks2], Al1 = pl1[2*ks2], Al2 = pl0[2*ks2+1], Al3 = pl1[2*ks2+1];
            #pragma unroll
            for (int dt = 0; dt < 12; dt++) {
                u32 boff = (u32)(((dt*8 + (lane & 7))*VS + ks2*16 + ((lane >> 3) & 1)*8) * 2);
                u32 bh0,bh1, bl0,bl1;
                ldm_x2(bh0,bh1, sbase + O_VH + boff);
                ldm_x2(bl0,bl1, sbase + O_VL + boff);
                mma_bf16(oC[dt], Ah0,Ah1,Ah2,Ah3, bh0,bh1);
                mma_bf16(oC[dt], Ah0,Ah1,Ah2,Ah3, bl0,bl1);
                mma_bf16(oC[dt], Al0,Al1,Al2,Al3, bh0,bh1);
            }
        }
        __syncthreads();   // tiles may be restaged next iteration
    }

    // ---- row-sum reduce, normalize, store ----
    ls01 += __shfl_xor_sync(0xffffffffu, ls01, 1);
    ls01 += __shfl_xor_sync(0xffffffffu, ls01, 2);
    ls23 += __shfl_xor_sync(0xffffffffu, ls23, 1);
    ls23 += __shfl_xor_sync(0xffffffffu, ls23, 2);
    float i01 = 1.f/ls01, i23 = 1.f/ls23;
    int rA = t0 + r0 + (lane >> 2);
    int colb = 2*(lane & 3);
    #pragma unroll
    for (int dt = 0; dt < 12; dt++) {
        float2 v0 = make_float2(oC[dt][0]*i01, oC[dt][1]*i01);
        float2 v1 = make_float2(oC[dt][2]*i23, oC[dt][3]*i23);
        *(float2*)&g_o[((size_t)rA*HEADS + h)*HD + dt*8 + colb] = v0;
        *(float2*)&g_o[((size_t)(rA+8)*HEADS + h)*HD + dt*8 + colb] = v1;
    }
}

// ---------------- grouped reduce ----------------
__global__ __launch_bounds__(256) void reduce_kernel(
    const float* __restrict__ W2, float* __restrict__ out)
{
    int tile = blockIdx.x;
    int e = g_tile_e[tile];
    if (e < 0) return;
    int c0 = blockIdx.y*64;
    int row0 = g_tile_row0[tile], nr = g_tile_nr[tile];
    extern __shared__ __align__(16) float rsm[];
    float* Os  = rsm;               // 64*98
    float* W2t = rsm + 64*98;       // 64*98
    __shared__ int   prs[64];
    __shared__ float gs[64];
    int tid = threadIdx.x;
    int ty = tid >> 4, tx = tid & 15;
    if (tid < 64) {
        int p = (tid < nr) ? g_pairs[row0 + tid] : -1;
        prs[tid] = p;
        gs[tid]  = (p >= 0) ? g_gates[p] : 0.f;
    }
    __syncthreads();
    for (int l = tid; l < 64*HD; l += 256) {
        int r = l / HD, d = l % HD;
        int p = prs[r];
        Os[r*98 + d] = (p >= 0) ? g_o[(size_t)p*HD + d]*gs[r] : 0.f;
    }
    const float* Wb = W2 + (size_t)e*HD*DIMX;
    for (int l = tid; l < HD*64; l += 256) {
        int d = l >> 6, c = l & 63;
        W2t[c*98 + d] = Wb[(size_t)d*DIMX + c0 + c];
    }
    __syncthreads();

    u64 acc[4][4];
    #pragma unroll
    for (int a = 0; a < 4; a++)
        #pragma unroll
        for (int c = 0; c < 4; c++) acc[a][c] = 0ULL;

    #pragma unroll 2
    for (int dp2 = 0; dp2 < HD/2; dp2++) {
        u64 a0 = lds64(&Os[(ty*4+0)*98 + 2*dp2]);
        u64 a1 = lds64(&Os[(ty*4+1)*98 + 2*dp2]);
        u64 a2 = lds64(&Os[(ty*4+2)*98 + 2*dp2]);
        u64 a3 = lds64(&Os[(ty*4+3)*98 + 2*dp2]);
        #pragma unroll
        for (int cj = 0; cj < 4; cj++) {
            u64 bv = lds64(&W2t[(tx+16*cj)*98 + 2*dp2]);
            ffma2(acc[0][cj], a0, bv); ffma2(acc[1][cj], a1, bv);
            ffma2(acc[2][cj], a2, bv); ffma2(acc[3][cj], a3, bv);
        }
    }
    #pragma unroll
    for (int ri = 0; ri < 4; ri++) {
        int p = prs[ty*4 + ri];
        if (p >= 0) {
            int t = p >> 3;
            float* op = out + (size_t)t*DIMX + c0;
            #pragma unroll
            for (int cj = 0; cj < 4; cj++)
                atomicAdd(op + tx + 16*cj, hadd2(acc[ri][cj]));
        }
    }
}

// ---------------- launch ----------------
extern "C" void kernel_launch(void* const* d_in, const int* in_sizes, int n_in,
                              void* d_out, int out_size)
{
    const float* x    = (const float*)d_in[0];
    const float* Wg   = (const float*)d_in[1];
    const float* W1   = (const float*)d_in[2];
    const float* W2   = (const float*)d_in[3];
    const float* Wkv  = (const float*)d_in[4];
    const float* bkv  = (const float*)d_in[5];
    const int*   task = (const int*)  d_in[6];
    float* out = (float*)d_out;

    const int reduce_smem = (64*98 * 2) * (int)sizeof(float);
    cudaFuncSetAttribute(attn_mma_kernel, cudaFuncAttributeMaxDynamicSharedMemorySize, ATTN_SMEM);
    cudaFuncSetAttribute(reduce_kernel,   cudaFuncAttributeMaxDynamicSharedMemorySize, reduce_smem);

    init_kernel<<<(OUT_N + 255)/256, 256>>>(out);
    gate_kernel<<<TOK, 128>>>(x, Wg, task);
    scan_kernel<<<1, 32>>>(out, out_size);
    scatter_kernel<<<NPAIR/256, 256>>>();
    kv_kernel<<<dim3(TOK/64, 2), 256>>>(x, Wkv, bkv);
    q_kernel<<<MAX_TILES, 256>>>(x, W1);
    attn_mma_kernel<<<dim3(NN/128, HEADS, BB), 256, ATTN_SMEM>>>();
    reduce_kernel<<<dim3(MAX_TILES, DIMX/64), 256, reduce_smem>>>(W2, out);
}